// round 14
// baseline (speedup 1.0000x reference)
#include <cuda_runtime.h>
#include <cuda_bf16.h>

// NURBS surface evaluation, degree 3 x 3, 32x32 control points, uniform
// clamped knots. S*F = 32 slices, P = 200000 points each.
//
// R9: L1TEX was 93.6% with random-gather LDS.64/LDS.32 (conflict mult ~3.4x).
//  * Packed-xyz patch rows read as 3x fully-useful LDS.128 (192B, 12 instr/pt
//    instead of 32). Alignment of 3*sv handled by storing 4 copies of the CP
//    plane, copy m pre-shifted by m floats; a point uses copy (sv & 3) so
//    m + 3*sv = 0 (mod 4) -> every LDS.128 is 16B-aligned.
//  * Row stride 100 floats ( = 4 mod 32 banks) so su rotates banks.
//  * 8 points/thread, 2048 points/block to amortize the 4x staging writes;
//    outputs flushed per 4-point group to bound register pressure.

#define SFCOUNT 32
#define NCP     32
#define RSTRIDE 100          // floats per row in each copy (multiple of 4)
#define COPYSZ  (NCP * RSTRIDE)
#define SMEMSZ  (4 * COPYSZ * sizeof(float))   // 51200 B
#define PPT     8            // points per thread
#define TPB     256

__device__ __forceinline__ void eval_basis(float uu, float b[4], float d[4], int& si_out)
{
    float x  = uu * 29.0f;
    float fs = floorf(x);
    int   si = (int)fs;
    si = max(0, min(si, 28));
    fs = (float)si;

    float t  = x - fs;        // left1
    float r1 = 1.0f - t;      // right1

    float km1 = (float)max(si - 1, 0);
    float km2 = (float)max(si - 2, 0);
    float kp2 = (float)min(si + 2, 29);
    float kp3 = (float)min(si + 3, 29);
    float left2  = x - km1;
    float left3  = x - km2;
    float right2 = kp2 - x;
    float right3 = kp3 - x;

    // All Cox-de Boor denominators in {1,2,3}, selected by span.
    bool e0  = (si == 0);
    bool e1  = (si == 1);
    bool e27 = (si == 27);
    bool e28 = (si == 28);
    const float third = 1.0f / 3.0f;
    float inv20 = e0  ? 1.0f : 0.5f;
    float inv21 = e28 ? 1.0f : 0.5f;
    float inv30 = e0  ? 1.0f : (e1  ? 0.5f : third);
    float inv31 = (e0 || e28) ? 0.5f : third;
    float inv32 = e28 ? 1.0f : (e27 ? 0.5f : third);

    float tA  = r1 * inv20;
    float B20 = r1 * tA;
    float sv  = left2 * tA;
    float tB  = t * inv21;
    float B21 = fmaf(right2, tB, sv);
    float B22 = t * tB;

    float t0 = B20 * inv30;
    b[0] = r1 * t0;
    sv   = left3 * t0;
    float t1 = B21 * inv31;
    b[1] = fmaf(right2, t1, sv);
    sv   = left2 * t1;
    float t2 = B22 * inv32;
    b[2] = fmaf(right3, t2, sv);
    b[3] = t * t2;

    d[0] = -t0;
    d[1] = t0 - t1;
    d[2] = t1 - t2;
    d[3] = t2;

    si_out = si;
}

__global__ __launch_bounds__(TPB)
void nurbs_kernel(const float* __restrict__ ev,
                  const float* __restrict__ cp,
                  float* __restrict__ out,
                  int P)
{
    extern __shared__ float scp[];   // [4 copies][32 rows][RSTRIDE]

    const int sf = blockIdx.y;
    const float* cpb = cp + (size_t)sf * (NCP * NCP * 3);

    // Stage CPs: packed xyz rows, 4 shifted copies for LDS.128 alignment.
    for (int k = threadIdx.x; k < NCP * NCP; k += TPB) {
        int iu = k >> 5;
        int iv = k & 31;
        float x = cpb[3 * k + 0];
        float y = cpb[3 * k + 1];
        float z = cpb[3 * k + 2];
#pragma unroll
        for (int m = 0; m < 4; m++) {
            float* row = scp + (m * NCP + iu) * RSTRIDE + m + 3 * iv;
            row[0] = x; row[1] = y; row[2] = z;
        }
    }
    __syncthreads();

    const int p0 = (blockIdx.x * TPB + threadIdx.x) * PPT;
    if (p0 >= P) return;   // P % PPT == 0, no partial threads

    const size_t slice = (size_t)sf * P;

#pragma unroll
    for (int g = 0; g < PPT / 4; g++) {
        const int pg = p0 + g * 4;

        const float4* ev4 = reinterpret_cast<const float4*>(ev + (slice + pg) * 2);
        float4 e0v = ev4[0];
        float4 e1v = ev4[1];
        float uvu[4] = {e0v.x, e0v.z, e1v.x, e1v.z};
        float uvv[4] = {e0v.y, e0v.w, e1v.y, e1v.w};

        float4 outpt[3];
        float4 outn [3];
        float* rp = reinterpret_cast<float*>(outpt);
        float* rn = reinterpret_cast<float*>(outn);

#pragma unroll
        for (int q = 0; q < 4; q++) {
            float bu[4], du[4], bv[4], dv[4];
            int su, svi;
            eval_basis(uvu[q], bu, du, su);
            eval_basis(uvv[q], bv, dv, svi);

            float px = 0.f, py = 0.f, pz = 0.f;
            float ax = 0.f, ay = 0.f, az = 0.f;
            float cx = 0.f, cy = 0.f, cz = 0.f;

            const int m = svi & 3;
            // float index divisible by 4 by construction
            const float4* base = reinterpret_cast<const float4*>(
                scp + (m * NCP + su) * RSTRIDE + m + 3 * svi);

#pragma unroll
            for (int i = 0; i < 4; i++) {
                const float4* r = base + i * (RSTRIDE / 4);
                float4 f0 = r[0];
                float4 f1 = r[1];
                float4 f2 = r[2];
                // f0 = x0 y0 z0 x1 | f1 = y1 z1 x2 y2 | f2 = z2 x3 y3 z3

                float rx = fmaf(bv[3], f2.y, fmaf(bv[2], f1.z, fmaf(bv[1], f0.w, bv[0] * f0.x)));
                float ry = fmaf(bv[3], f2.z, fmaf(bv[2], f1.w, fmaf(bv[1], f1.x, bv[0] * f0.y)));
                float rz = fmaf(bv[3], f2.w, fmaf(bv[2], f2.x, fmaf(bv[1], f1.y, bv[0] * f0.z)));
                float qx = fmaf(dv[3], f2.y, fmaf(dv[2], f1.z, fmaf(dv[1], f0.w, dv[0] * f0.x)));
                float qy = fmaf(dv[3], f2.z, fmaf(dv[2], f1.w, fmaf(dv[1], f1.x, dv[0] * f0.y)));
                float qz = fmaf(dv[3], f2.w, fmaf(dv[2], f2.x, fmaf(dv[1], f1.y, dv[0] * f0.z)));

                px = fmaf(bu[i], rx, px);
                py = fmaf(bu[i], ry, py);
                pz = fmaf(bu[i], rz, pz);
                ax = fmaf(du[i], rx, ax);
                ay = fmaf(du[i], ry, ay);
                az = fmaf(du[i], rz, az);
                cx = fmaf(bu[i], qx, cx);
                cy = fmaf(bu[i], qy, cy);
                cz = fmaf(bu[i], qz, cz);
            }

            float nx = fmaf(ay, cz, -(az * cy));
            float ny = fmaf(az, cx, -(ax * cz));
            float nz = fmaf(ax, cy, -(ay * cx));

            float n2 = fmaf(nx, nx, fmaf(ny, ny, nz * nz));
            n2 = fmaxf(n2, 1.0e-30f);
            float h = 0.5f * n2;
            float y = __uint_as_float(0x5f3759dfu - (__float_as_uint(n2) >> 1));
            y = y * fmaf(-h, y * y, 1.5f);
            y = y * fmaf(-h, y * y, 1.5f);

            rp[q * 3 + 0] = px;
            rp[q * 3 + 1] = py;
            rp[q * 3 + 2] = pz;
            rn[q * 3 + 0] = nx * y;
            rn[q * 3 + 1] = ny * y;
            rn[q * 3 + 2] = nz * y;
        }

        float4* opt = reinterpret_cast<float4*>(out + (slice + pg) * 3);
        opt[0] = outpt[0];
        opt[1] = outpt[1];
        opt[2] = outpt[2];
        float4* onr = reinterpret_cast<float4*>(out + (size_t)SFCOUNT * P * 3 +
                                                (slice + pg) * 3);
        onr[0] = outn[0];
        onr[1] = outn[1];
        onr[2] = outn[2];
    }
}

extern "C" void kernel_launch(void* const* d_in, const int* in_sizes, int n_in,
                              void* d_out, int out_size)
{
    const float* ev = (const float*)d_in[0];   // [S,F,P,2] f32
    const float* cp = (const float*)d_in[1];   // [S,F,32,32,3] f32
    float* out = (float*)d_out;                // [2,S,F,P,3] f32 (pt, normals)

    const int P = in_sizes[0] / (SFCOUNT * 2);

    cudaFuncSetAttribute(nurbs_kernel,
                         cudaFuncAttributeMaxDynamicSharedMemorySize,
                         (int)SMEMSZ);

    const int pts_per_block = TPB * PPT;
    dim3 grid((P + pts_per_block - 1) / pts_per_block, SFCOUNT);
    nurbs_kernel<<<grid, TPB, SMEMSZ>>>(ev, cp, out, P);
}